// round 1
// baseline (speedup 1.0000x reference)
#include <cuda_runtime.h>
#include <math.h>

// MoE top-1: gate (16x512 @ 512x4 -> softmax -> argmax), then per-batch
// selected expert: conv3x3(128->128)+bias -> gelu(exact) -> conv3x3+bias,
// scaled by top-1 softmax prob.
//
// Conv as implicit GEMM: per block, output tile = 128 co x 128 pixels
// (8 rows x 16 cols spatial). 256 threads, each owns an 8co x 8px register
// tile (two co-groups of 4, two row-groups of 4). K = 128 ci x 9 taps,
// chunked by 8 ci through shared memory.

#define NB   16
#define CCH  128
#define HW   64
#define ENUM 4
#define TH   8
#define TW   16
#define TC   8
#define ISR  10   // input tile rows (TH + halo 2)
#define ISC  18   // input tile cols actually used (TW + halo 2)
#define ISS  33   // padded row stride (odd -> conflict-free LDS pattern)

__device__ int   g_sel[NB];
__device__ float g_val[NB];
__device__ float g_h[(size_t)NB * CCH * HW * HW];   // 32 MB intermediate

// ---------------------------------------------------------------------------
__global__ void gate_kernel(const float* __restrict__ text,
                            const float* __restrict__ gw)
{
    __shared__ float logits[NB][ENUM];
    int t = threadIdx.x;
    if (t < NB * ENUM) {
        int b = t >> 2, e = t & 3;
        const float* tp = text + b * 512;
        const float* wp = gw + e * 512;
        float s = 0.f;
        #pragma unroll 8
        for (int k = 0; k < 512; k++) s += tp[k] * wp[k];
        logits[b][e] = s;
    }
    __syncthreads();
    if (t < NB) {
        float m = logits[t][0]; int am = 0;
        #pragma unroll
        for (int e = 1; e < ENUM; e++) {
            float v = logits[t][e];
            if (v > m) { m = v; am = e; }
        }
        float sum = 0.f;
        #pragma unroll
        for (int e = 0; e < ENUM; e++) sum += expf(logits[t][e] - m);
        g_sel[t] = am;
        g_val[t] = 1.f / sum;   // softmax prob of the argmax
    }
}

// ---------------------------------------------------------------------------
template<bool GELU>
__global__ __launch_bounds__(256, 2) void conv_kernel(
    const float* __restrict__ in,    // used when GELU (layer 1): x
    const float* __restrict__ w,     // [E][CO][CI][3][3]
    const float* __restrict__ bias,  // [E][CO]
    float* __restrict__ out)         // used when !GELU (layer 2): final out
{
    __shared__ float Ws[TC][9][CCH];       // [ci][tap][co]
    __shared__ float Is[TC][ISR][ISS];     // [ci][row][col]

    const int b    = blockIdx.y;
    const int tile = blockIdx.x;
    const int y0 = (tile >> 2) * TH;       // 8 tile rows
    const int x0 = (tile & 3) * TW;        // 4 tile cols
    const int e  = g_sel[b];

    const float* __restrict__ wexp = w + (size_t)e * CCH * CCH * 9;
    const float* __restrict__ inb  = (GELU ? in : (const float*)g_h)
                                     + (size_t)b * CCH * HW * HW;
    float* __restrict__ outp = GELU ? g_h : out;

    const int t  = threadIdx.x;
    const int tx = t & 15, ty = t >> 4;
    const int rA = tx >> 2;          // 0..3: output row within tile (group A)
    const int c0 = (tx & 3) << 2;    // 0,4,8,12: output col base

    float acc[2][2][4][4];           // [co-group][row-group][co][px]
    #pragma unroll
    for (int a = 0; a < 2; a++)
        #pragma unroll
        for (int g = 0; g < 2; g++)
            #pragma unroll
            for (int i = 0; i < 4; i++)
                #pragma unroll
                for (int j = 0; j < 4; j++) acc[a][g][i][j] = 0.f;

    for (int ci0 = 0; ci0 < CCH; ci0 += TC) {
        // ---- stage weights: 128co x (8ci x 9taps = 72 contiguous floats) ----
        // 2304 float4 total, 9 per thread, exact.
        #pragma unroll
        for (int it = 0; it < 9; it++) {
            int idx = t + it * 256;
            int co = idx / 18, q = idx % 18;
            const float4 v = *reinterpret_cast<const float4*>(
                wexp + (size_t)co * (CCH * 9) + ci0 * 9 + q * 4);
            float vv[4] = {v.x, v.y, v.z, v.w};
            int k4 = q * 4;
            #pragma unroll
            for (int j = 0; j < 4; j++) {
                int kk = k4 + j;
                Ws[kk / 9][kk % 9][co] = vv[j];
            }
        }
        // ---- stage input halo tile: 8ci x 10 x 18, zero-padded at borders ----
        #pragma unroll
        for (int it = 0; it < 6; it++) {
            int idx = t + it * 256;
            if (idx < TC * ISR * ISC) {
                int ci  = idx / (ISR * ISC);
                int rem = idx % (ISR * ISC);
                int row = rem / ISC, col = rem % ISC;
                int gy = y0 - 1 + row, gx = x0 - 1 + col;
                float v = 0.f;
                if ((unsigned)gy < HW && (unsigned)gx < HW)
                    v = inb[(size_t)(ci0 + ci) * (HW * HW) + gy * HW + gx];
                Is[ci][row][col] = v;
            }
        }
        __syncthreads();

        // ---- compute: per ci, per ky: 12 input LDS, then 3kx x 8co x 8px FFMA
        #pragma unroll 2
        for (int ci = 0; ci < TC; ci++) {
            #pragma unroll
            for (int ky = 0; ky < 3; ky++) {
                float a6[6], b6[6];
                #pragma unroll
                for (int j = 0; j < 6; j++) {
                    a6[j] = Is[ci][rA + ky][c0 + j];
                    b6[j] = Is[ci][rA + 4 + ky][c0 + j];
                }
                #pragma unroll
                for (int kx = 0; kx < 3; kx++) {
                    float wA[4], wB[4];
                    #pragma unroll
                    for (int i = 0; i < 4; i++) {
                        wA[i] = Ws[ci][ky * 3 + kx][ty * 4 + i];
                        wB[i] = Ws[ci][ky * 3 + kx][ty * 4 + 64 + i];
                    }
                    #pragma unroll
                    for (int i = 0; i < 4; i++)
                        #pragma unroll
                        for (int j = 0; j < 4; j++) {
                            acc[0][0][i][j] += wA[i] * a6[j + kx];
                            acc[0][1][i][j] += wA[i] * b6[j + kx];
                            acc[1][0][i][j] += wB[i] * a6[j + kx];
                            acc[1][1][i][j] += wB[i] * b6[j + kx];
                        }
                }
            }
        }
        __syncthreads();
    }

    // ---- epilogue ----
    const float scale = g_val[b];
    const float* __restrict__ be = bias + e * CCH;
    #pragma unroll
    for (int a = 0; a < 2; a++) {
        #pragma unroll
        for (int i = 0; i < 4; i++) {
            int co = ty * 4 + i + a * 64;
            float bv = be[co];
            #pragma unroll
            for (int g = 0; g < 2; g++) {
                int gy = y0 + rA + g * 4;
                float4 o;
                float* op = &o.x;
                #pragma unroll
                for (int j = 0; j < 4; j++) {
                    float v = acc[a][g][i][j] + bv;
                    if (GELU)
                        v = 0.5f * v * (1.f + erff(v * 0.70710678118654752f));
                    else
                        v *= scale;
                    op[j] = v;
                }
                *reinterpret_cast<float4*>(
                    outp + ((size_t)(b * CCH + co) * HW + gy) * HW + x0 + c0) = o;
            }
        }
    }
}

// ---------------------------------------------------------------------------
extern "C" void kernel_launch(void* const* d_in, const int* in_sizes, int n_in,
                              void* d_out, int out_size)
{
    const float* x    = (const float*)d_in[0];
    const float* text = (const float*)d_in[1];
    const float* gw   = (const float*)d_in[2];
    const float* w1   = (const float*)d_in[3];
    const float* b1   = (const float*)d_in[4];
    const float* w2   = (const float*)d_in[5];
    const float* b2   = (const float*)d_in[6];
    float* out = (float*)d_out;

    gate_kernel<<<1, 64>>>(text, gw);

    dim3 grid(32, NB);   // 8x4 spatial tiles x 16 batch
    conv_kernel<true ><<<grid, 256>>>(x,       w1, b1, nullptr);
    conv_kernel<false><<<grid, 256>>>(nullptr, w2, b2, out);
}

// round 4
// speedup vs baseline: 2.1884x; 2.1884x over previous
#include <cuda_runtime.h>
#include <cuda_bf16.h>
#include <cstdint>
#include <math.h>

#define NB 16
#define CC 128
#define HW 64
#define EN 4
#define NPX 4096           // 64*64 pixels per image
#define NCHUNKS 72         // 9 taps * 8 ci-chunks of 16

// ---------------- device scratch ----------------
__device__ int      g_sel[NB];
__device__ float    g_val[NB];
__device__ uint16_t g_xh[(size_t)NB*NPX*CC];   // x  hi bf16, [b][px][ci]
__device__ uint16_t g_xl[(size_t)NB*NPX*CC];   // x  lo bf16
__device__ uint16_t g_hh[(size_t)NB*NPX*CC];   // gelu(h) hi
__device__ uint16_t g_hl[(size_t)NB*NPX*CC];   // gelu(h) lo
__device__ uint16_t g_w1h[(size_t)EN*9*CC*CC]; // [e][tap][co][ci]
__device__ uint16_t g_w1l[(size_t)EN*9*CC*CC];
__device__ uint16_t g_w2h[(size_t)EN*9*CC*CC];
__device__ uint16_t g_w2l[(size_t)EN*9*CC*CC];

// ---------------- helpers ----------------
__device__ __forceinline__ uint32_t smem_u32(const void* p) {
    uint32_t a;
    asm("{ .reg .u64 t; cvta.to.shared.u64 t, %1; cvt.u32.u64 %0, t; }"
        : "=r"(a) : "l"(p));
    return a;
}
__device__ __forceinline__ void cp16(uint32_t d, const void* s, bool ok) {
    asm volatile("cp.async.cg.shared.global [%0], [%1], 16, %2;"
        :: "r"(d), "l"(s), "r"(ok ? 16u : 0u) : "memory");
}
#define CP_COMMIT() asm volatile("cp.async.commit_group;" ::: "memory")
#define CP_WAIT1()  asm volatile("cp.async.wait_group 1;" ::: "memory")
#define CP_WAIT0()  asm volatile("cp.async.wait_group 0;" ::: "memory")

#define LDM(r, a) \
    asm volatile("ldmatrix.sync.aligned.m8n8.x4.shared.b16 {%0,%1,%2,%3}, [%4];" \
        : "=r"((r)[0]), "=r"((r)[1]), "=r"((r)[2]), "=r"((r)[3]) : "r"(a))

#define MMA(c, a, b) \
    asm volatile("mma.sync.aligned.m16n8k16.row.col.f32.bf16.bf16.f32 " \
        "{%0,%1,%2,%3},{%4,%5,%6,%7},{%8,%9},{%0,%1,%2,%3};" \
        : "+f"((c)[0]), "+f"((c)[1]), "+f"((c)[2]), "+f"((c)[3]) \
        : "r"((a)[0]), "r"((a)[1]), "r"((a)[2]), "r"((a)[3]), \
          "r"((b)[0]), "r"((b)[1]))

__device__ __forceinline__ void split2(float v, uint16_t& h, uint16_t& l) {
    __nv_bfloat16 hb = __float2bfloat16(v);
    float r = v - __bfloat162float(hb);
    __nv_bfloat16 lb = __float2bfloat16(r);
    h = __bfloat16_as_ushort(hb);
    l = __bfloat16_as_ushort(lb);
}
__device__ __forceinline__ uint32_t pack_hl(float v) {
    uint16_t h, l; split2(v, h, l);
    return ((uint32_t)l << 16) | (uint32_t)h;
}
__device__ __forceinline__ float gelu_f(float v) {
    return 0.5f * v * (1.f + erff(v * 0.70710678118654752f));
}

// ---------------------------------------------------------------------------
__global__ void gate_kernel(const float* __restrict__ text, const float* __restrict__ gw)
{
    __shared__ float lg[EN];
    int b = blockIdx.x, wid = threadIdx.x >> 5, lid = threadIdx.x & 31;
    const float* tp = text + b * 512;
    const float* wp = gw + wid * 512;
    float s = 0.f;
    #pragma unroll 4
    for (int k = lid; k < 512; k += 32) s += tp[k] * wp[k];
    #pragma unroll
    for (int o = 16; o; o >>= 1) s += __shfl_xor_sync(~0u, s, o);
    if (lid == 0) lg[wid] = s;
    __syncthreads();
    if (threadIdx.x == 0) {
        float m = lg[0]; int am = 0;
        #pragma unroll
        for (int e = 1; e < EN; e++) if (lg[e] > m) { m = lg[e]; am = e; }
        float sum = 0.f;
        #pragma unroll
        for (int e = 0; e < EN; e++) sum += expf(lg[e] - m);
        g_sel[b] = am;
        g_val[b] = 1.f / sum;
    }
}

// w[e][co][ci][3][3] fp32 -> hi/lo bf16 at [e][tap][co][ci]
__global__ void prep_w_kernel(const float* __restrict__ w,
                              uint16_t* __restrict__ oh, uint16_t* __restrict__ ol)
{
    int g = blockIdx.x * blockDim.x + threadIdx.x;
    if (g >= EN * 9 * CC * CC) return;
    int ci = g & 127, co = (g >> 7) & 127, tap = (g >> 14) % 9, e = g / (9 * CC * CC);
    float v = w[((size_t)(e * CC + co) * CC + ci) * 9 + tap];
    uint16_t h, l; split2(v, h, l);
    oh[g] = h; ol[g] = l;
}

// x[b][ci][px] fp32 -> xT hi/lo [b][px][ci] (32x32 SMEM tile transpose)
__global__ void prep_x_kernel(const float* __restrict__ x)
{
    __shared__ float s[32][33];
    int b = blockIdx.z, ci0 = blockIdx.y * 32, px0 = blockIdx.x * 32;
    int pl = threadIdx.x & 31, cl = threadIdx.x >> 5;   // cl: 0..7
    #pragma unroll
    for (int i = 0; i < 4; i++) {
        int ci = cl + i * 8;
        s[ci][pl] = x[((size_t)(b * CC + ci0 + ci)) * NPX + px0 + pl];
    }
    __syncthreads();
    #pragma unroll
    for (int i = 0; i < 4; i++) {
        int px = cl + i * 8;
        uint16_t h, l; split2(s[pl][px], h, l);
        size_t o = ((size_t)b * NPX + px0 + px) * CC + ci0 + pl;
        g_xh[o] = h; g_xl[o] = l;
    }
}

// ---------------------------------------------------------------------------
// Per CTA: image b, 128 pixels (2 rows), 128 co. mma.sync m16n8k16 bf16,
// split hi/lo 3-product. Double-buffered cp.async staging.
// SMEM stage layout (per stage 16KB): Ahi@0, Alo@4096, Bhi@8192, Blo@12288;
// each matrix 128 rows x 32B, 16B halves swizzled by ((kh + (row>>2)) & 1).
template<bool L1>
__global__ void __launch_bounds__(256) conv_mma(const float* __restrict__ bias,
                                                float* __restrict__ out)
{
    __shared__ __align__(16) uint8_t pool[32768];
    const int t = threadIdx.x, wid = t >> 5, lid = t & 31;
    const int b = blockIdx.y, y0 = blockIdx.x * 2;
    const int e = g_sel[b];
    const uint32_t sb = smem_u32(pool);

    const uint16_t* __restrict__ wh = (L1 ? g_w1h : g_w2h) + (size_t)e * 9 * CC * CC;
    const uint16_t* __restrict__ wl = (L1 ? g_w1l : g_w2l) + (size_t)e * 9 * CC * CC;
    const uint16_t* __restrict__ xh = (L1 ? g_xh : g_hh) + (size_t)b * NPX * CC;
    const uint16_t* __restrict__ xl = (L1 ? g_xl : g_hl) + (size_t)b * NPX * CC;

    // staging geometry: thread -> (row 0..127, k-half 0..1), one 16B granule per matrix
    const int srow = t >> 1, skh = t & 1;
    const uint32_t sdo = srow * 32 + (((skh + (srow >> 2)) & 1) << 4);

    auto stage = [&](int it, int buf) {
        const int tap = it >> 3, ci0 = (it & 7) << 4;
        const int ty = tap / 3;
        const int dy = ty - 1, dx = tap - ty * 3 - 1;
        const uint32_t d = sb + buf * 16384 + sdo;
        const size_t wo = ((size_t)tap * CC + srow) * CC + ci0 + skh * 8;
        cp16(d,        wh + wo, true);
        cp16(d + 4096, wl + wo, true);
        const int gy = y0 + (srow >> 6) + dy, gx = (srow & 63) + dx;
        const bool ok = ((unsigned)gy < HW) && ((unsigned)gx < HW);
        const size_t po = ok ? ((size_t)(gy * HW + gx) * CC + ci0 + skh * 8) : 0;
        cp16(d + 8192,  xh + po, ok);
        cp16(d + 12288, xl + po, ok);
        CP_COMMIT();
    };

    // compute geometry
    const int Mw = (wid >> 2) * 64, Nw = (wid & 3) * 32;
    const int arow0 = (lid & 7) + (((lid >> 3) & 1) << 3);
    const int akh   = lid >> 4;
    const int brow0 = (lid & 7) + (((lid >> 4) & 1) << 3);
    const int bkh   = (lid >> 3) & 1;

    float acc[4][4][4];
    #pragma unroll
    for (int mi = 0; mi < 4; mi++)
        #pragma unroll
        for (int nj = 0; nj < 4; nj++)
            #pragma unroll
            for (int k = 0; k < 4; k++) acc[mi][nj][k] = 0.f;

    stage(0, 0);
    for (int it = 0; it < NCHUNKS; it++) {
        if (it + 1 < NCHUNKS) { stage(it + 1, (it + 1) & 1); CP_WAIT1(); }
        else                  { CP_WAIT0(); }
        __syncthreads();
        const uint32_t base = sb + (it & 1) * 16384;

        uint32_t aH[4][4], aL[4][4], bH[2][4], bL[2][4];
        #pragma unroll
        for (int mi = 0; mi < 4; mi++) {
            int r = Mw + mi * 16 + arow0;
            uint32_t ad = base + r * 32 + (((akh + (r >> 2)) & 1) << 4);
            LDM(aH[mi], ad);
            LDM(aL[mi], ad + 4096);
        }
        #pragma unroll
        for (int np = 0; np < 2; np++) {
            int r = Nw + np * 16 + brow0;
            uint32_t bd = base + 8192 + r * 32 + (((bkh + (r >> 2)) & 1) << 4);
            LDM(bH[np], bd);
            LDM(bL[np], bd + 4096);
        }
        #pragma unroll
        for (int mi = 0; mi < 4; mi++)
            #pragma unroll
            for (int nj = 0; nj < 4; nj++) {
                uint32_t* bh = &bH[nj >> 1][(nj & 1) * 2];
                uint32_t* bl = &bL[nj >> 1][(nj & 1) * 2];
                MMA(acc[mi][nj], aH[mi], bh);
                MMA(acc[mi][nj], aH[mi], bl);
                MMA(acc[mi][nj], aL[mi], bh);
            }
        __syncthreads();
    }

    // ---------------- epilogue ----------------
    const float scale = g_val[b];
    if (L1) {
        uint32_t* sT = (uint32_t*)pool;             // [32 px][132] packed hi|lo
        for (int r = 0; r < 4; r++) {
            if ((wid & 3) == r) {
                #pragma unroll
                for (int mi = 0; mi < 4; mi++) {
                    int co = Mw + mi * 16 + (lid >> 2);
                    float b0 = bias[e * CC + co], b1 = bias[e * CC + co + 8];
                    #pragma unroll
                    for (int nj = 0; nj < 4; nj++) {
                        int n = nj * 8 + (lid & 3) * 2;
                        float* c = acc[mi][nj];
                        sT[n * 132 + co]           = pack_hl(gelu_f(c[0] + b0));
                        sT[(n + 1) * 132 + co]     = pack_hl(gelu_f(c[1] + b0));
                        sT[n * 132 + co + 8]       = pack_hl(gelu_f(c[2] + b1));
                        sT[(n + 1) * 132 + co + 8] = pack_hl(gelu_f(c[3] + b1));
                    }
                }
            }
            __syncthreads();
            {
                int pl = t >> 3, cil = (t & 7) * 16;
                int n = r * 32 + pl;
                int gy = y0 + (n >> 6), gx = n & 63;
                size_t o = (size_t)b * NPX * CC + (size_t)(gy * HW + gx) * CC + cil;
                #pragma unroll
                for (int k = 0; k < 16; k++) {
                    uint32_t v = sT[pl * 132 + cil + k];
                    g_hh[o + k] = (uint16_t)v;
                    g_hl[o + k] = (uint16_t)(v >> 16);
                }
            }
            __syncthreads();
        }
    } else {
        float* sT = (float*)pool;                   // [128 co][36] fp32
        for (int r = 0; r < 4; r++) {
            if ((wid & 3) == r) {
                #pragma unroll
                for (int mi = 0; mi < 4; mi++) {
                    int co = Mw + mi * 16 + (lid >> 2);
                    float b0 = bias[e * CC + co], b1 = bias[e * CC + co + 8];
                    #pragma unroll
                    for (int nj = 0; nj < 4; nj++) {
                        int n = nj * 8 + (lid & 3) * 2;
                        float* c = acc[mi][nj];
                        sT[co * 36 + n]           = (c[0] + b0) * scale;
                        sT[co * 36 + n + 1]       = (c[1] + b0) * scale;
                        sT[(co + 8) * 36 + n]     = (c[2] + b1) * scale;
                        sT[(co + 8) * 36 + n + 1] = (c[3] + b1) * scale;
                    }
                }
            }
            __syncthreads();
            #pragma unroll
            for (int j = 0; j < 4; j++) {
                int co = j * 32 + (t >> 3);
                int f4 = t & 7;
                int n = r * 32 + f4 * 4;
                int gy = y0 + (n >> 6), gx = n & 63;
                float4 v = *(const float4*)&sT[co * 36 + f4 * 4];
                *(float4*)&out[((size_t)(b * CC + co)) * NPX + gy * HW + gx] = v;
            }
            __syncthreads();
        }
    }
}

// ---------------------------------------------------------------------------
extern "C" void kernel_launch(void* const* d_in, const int* in_sizes, int n_in,
                              void* d_out, int out_size)
{
    const float* x    = (const float*)d_in[0];
    const float* text = (const float*)d_in[1];
    const float* gw   = (const float*)d_in[2];
    const float* w1   = (const float*)d_in[3];
    const float* b1   = (const float*)d_in[4];
    const float* w2   = (const float*)d_in[5];
    const float* b2   = (const float*)d_in[6];
    float* out = (float*)d_out;

    gate_kernel<<<NB, 128>>>(text, gw);

    uint16_t *w1h, *w1l, *w2h, *w2l;
    cudaGetSymbolAddress((void**)&w1h, g_w1h);
    cudaGetSymbolAddress((void**)&w1l, g_w1l);
    cudaGetSymbolAddress((void**)&w2h, g_w2h);
    cudaGetSymbolAddress((void**)&w2l, g_w2l);
    const int wn = EN * 9 * CC * CC;
    prep_w_kernel<<<(wn + 255) / 256, 256>>>(w1, w1h, w1l);
    prep_w_kernel<<<(wn + 255) / 256, 256>>>(w2, w2h, w2l);

    dim3 pg(NPX / 32, CC / 32, NB);
    prep_x_kernel<<<pg, 256>>>(x);

    dim3 grid(HW / 2, NB);   // 32 x 16
    conv_mma<true ><<<grid, 256>>>(b1, nullptr);
    conv_mma<false><<<grid, 256>>>(b2, out);
}